// round 13
// baseline (speedup 1.0000x reference)
#include <cuda_runtime.h>
#include <cstdint>

#define S_LEN 2048
#define B_SZ  256
#define H_SZ  256
#define NI    128
#define NO    128

typedef unsigned long long ull;

// Scratch (allocation-free)
__device__ float g_Zx[(size_t)S_LEN * B_SZ * H_SZ];   // (t, b, h)
__device__ float g_H [(size_t)S_LEN * B_SZ * H_SZ];   // (t, b, k)
__device__ float g_sum[S_LEN][H_SZ];                  // per-step BN sum (RED)
__device__ float g_sq [S_LEN][H_SZ];                  // per-step BN sumsq (RED)
__device__ unsigned g_cnt[32];                        // padded step counter

__device__ __forceinline__ float gelu_f(float x) {
    return 0.5f * x * (1.0f + erff(x * 0.70710678118654752440f));
}

// ---- packed f32x2 helpers (sm_103a) ----
__device__ __forceinline__ void fma2(ull& d, ull a, ull b) {
    asm("fma.rn.f32x2 %0, %1, %2, %3;" : "=l"(d) : "l"(a), "l"(b), "l"(d));
}
__device__ __forceinline__ ull add2(ull a, ull b) {
    ull r; asm("add.rn.f32x2 %0, %1, %2;" : "=l"(r) : "l"(a), "l"(b)); return r;
}
__device__ __forceinline__ ull pack2(float x, float y) {
    ull r; asm("mov.b64 %0, {%1, %2};" : "=l"(r) : "f"(x), "f"(y)); return r;
}
__device__ __forceinline__ float2 unpack2(ull v) {
    float2 f; asm("mov.b64 {%0, %1}, %2;" : "=f"(f.x), "=f"(f.y) : "l"(v)); return f;
}

// ---- cluster / sync helpers ----
__device__ __forceinline__ unsigned ctarank() {
    unsigned r; asm("mov.u32 %0, %%cluster_ctarank;" : "=r"(r)); return r;
}
__device__ __forceinline__ unsigned smem_u32(const void* p) {
    return (unsigned)__cvta_generic_to_shared(p);
}
__device__ __forceinline__ unsigned mapa_peer(unsigned laddr, unsigned rank) {
    unsigned r;
    asm("mapa.shared::cluster.u32 %0, %1, %2;" : "=r"(r) : "r"(laddr), "r"(rank));
    return r;
}
__device__ __forceinline__ void st_cluster_f2(unsigned addr, float x, float y) {
    asm volatile("st.shared::cluster.v2.f32 [%0], {%1, %2};"
                 :: "r"(addr), "f"(x), "f"(y) : "memory");
}
__device__ __forceinline__ void cluster_sync_() {
    asm volatile("barrier.cluster.arrive.aligned;" ::: "memory");
    asm volatile("barrier.cluster.wait.aligned;" ::: "memory");
}
__device__ __forceinline__ void red_addf(float* p, float v) {
    asm volatile("red.global.add.f32 [%0], %1;" :: "l"(p), "f"(v) : "memory");
}

__global__ void init_kernel() {
    const size_t n = (size_t)S_LEN * H_SZ;
    const size_t stride = (size_t)gridDim.x * blockDim.x;
    for (size_t i = (size_t)blockIdx.x * blockDim.x + threadIdx.x; i < n; i += stride) {
        ((float*)g_sum)[i] = 0.f;
        ((float*)g_sq)[i]  = 0.f;
    }
    if (blockIdx.x == 0 && threadIdx.x < 32) g_cnt[threadIdx.x] = 0u;
}

// Pad kernel: aligns rec_kernel onto the ncu-profiled launch slot (#4).
__global__ void pad_kernel() { }

// ---------------------------------------------------------------------------
// Kernel A: Zx[t,b,n] = sum_i X[b,t,i] * W_ih[n,i] + b_ih[n]
// ---------------------------------------------------------------------------
__global__ void __launch_bounds__(256) proj_in_kernel(
    const float* __restrict__ X, const float* __restrict__ W_ih,
    const float* __restrict__ b_ih)
{
    __shared__ float As[16][132];
    __shared__ float Bs[16][68];
    const int tid = threadIdx.x;
    const int r0  = blockIdx.x * 128;
    const int n0  = blockIdx.y * 64;
    const int t   = r0 >> 8;
    const int b0  = r0 & 255;
    const int tx  = tid & 15, ty = tid >> 4;

    float acc[8][4];
    #pragma unroll
    for (int i = 0; i < 8; ++i)
        #pragma unroll
        for (int j = 0; j < 4; ++j) acc[i][j] = 0.f;

    const int kq = (tid & 3) * 4;
    const int am = tid >> 2;

    for (int k0 = 0; k0 < NI; k0 += 16) {
        #pragma unroll
        for (int h = 0; h < 2; ++h) {
            const int m = am + h * 64;
            const float4 v = *(const float4*)(X + (size_t)(b0 + m) * (S_LEN * NI)
                                              + (size_t)t * NI + k0 + kq);
            As[kq + 0][m] = v.x; As[kq + 1][m] = v.y;
            As[kq + 2][m] = v.z; As[kq + 3][m] = v.w;
        }
        {
            const float4 v = *(const float4*)(W_ih + (size_t)(n0 + am) * 384 + k0 + kq);
            Bs[kq + 0][am] = v.x; Bs[kq + 1][am] = v.y;
            Bs[kq + 2][am] = v.z; Bs[kq + 3][am] = v.w;
        }
        __syncthreads();
        #pragma unroll
        for (int kk = 0; kk < 16; ++kk) {
            const float4 a0 = *(const float4*)&As[kk][ty * 8];
            const float4 a1 = *(const float4*)&As[kk][ty * 8 + 4];
            const float4 bv = *(const float4*)&Bs[kk][tx * 4];
            const float a[8] = {a0.x, a0.y, a0.z, a0.w, a1.x, a1.y, a1.z, a1.w};
            const float bb[4] = {bv.x, bv.y, bv.z, bv.w};
            #pragma unroll
            for (int i = 0; i < 8; ++i)
                #pragma unroll
                for (int j = 0; j < 4; ++j) acc[i][j] = fmaf(a[i], bb[j], acc[i][j]);
        }
        __syncthreads();
    }
    const float4 bv = *(const float4*)(b_ih + n0 + tx * 4);
    #pragma unroll
    for (int i = 0; i < 8; ++i) {
        float4 o;
        o.x = acc[i][0] + bv.x; o.y = acc[i][1] + bv.y;
        o.z = acc[i][2] + bv.z; o.w = acc[i][3] + bv.w;
        *(float4*)(g_Zx + (size_t)(r0 + ty * 8 + i) * 256 + n0 + tx * 4) = o;
    }
}

// ---------------------------------------------------------------------------
// Kernel B: R6 k-split clustered recurrence, finalize split over 256 threads.
// (Exact restore of the 9.526 ms champion.)
// ---------------------------------------------------------------------------
__global__ void __launch_bounds__(256, 1) __cluster_dims__(2, 1, 1)
rec_kernel(const float* __restrict__ W_ih, const float* __restrict__ gamma,
           const float* __restrict__ beta)
{
    __shared__ float  h2[128][8];        // own k-half h, 4 rows dup pairs (4 KB)
    __shared__ float2 redb[2][4][128];   // own partials [kq][row][cp] (8 KB)
    __shared__ float2 zbuf[2][4][128];   // peer totals, parity (8 KB)

    const int tid  = threadIdx.x;
    const unsigned rank = ctarank();
    const int b0   = (blockIdx.x >> 1) * 4;
    const int kq   = tid >> 7;           // 0..1: 64-k quarter of own k-half
    const int cp   = tid & 127;          // col pair (matvec role)
    const int c2   = cp * 2;

    ull wreg[64];
    {
        const int kbase = NI + (int)rank * 128 + kq * 64;
        const float* w0p = W_ih + (size_t)c2 * 384 + kbase;
        const float* w1p = W_ih + (size_t)(c2 + 1) * 384 + kbase;
        #pragma unroll
        for (int i = 0; i < 64; ++i) wreg[i] = pack2(w0p[i], w1p[i]);
    }
    const float gam = gamma[tid];
    const float bet = beta[tid];

    volatile unsigned* vcnt = (volatile unsigned*)&g_cnt[0];

    for (int t = 0; t < S_LEN; ++t) {
        float zx0 = __ldcg(g_Zx + ((size_t)t * 256 + b0 + 0) * 256 + tid);
        float zx1 = __ldcg(g_Zx + ((size_t)t * 256 + b0 + 1) * 256 + tid);
        float zx2 = __ldcg(g_Zx + ((size_t)t * 256 + b0 + 2) * 256 + tid);
        float zx3 = __ldcg(g_Zx + ((size_t)t * 256 + b0 + 3) * 256 + tid);

        ull a0 = 0ull, a1 = 0ull, a2 = 0ull, a3 = 0ull;
        if (t > 0) {
            const int kb = kq * 64;
            #pragma unroll
            for (int i = 0; i < 64; ++i) {
                const ulonglong2 p01 = *(const ulonglong2*)&h2[kb + i][0];
                const ulonglong2 p23 = *(const ulonglong2*)&h2[kb + i][4];
                fma2(a0, p01.x, wreg[i]);
                fma2(a1, p01.y, wreg[i]);
                fma2(a2, p23.x, wreg[i]);
                fma2(a3, p23.y, wreg[i]);
            }
        }
        redb[kq][0][cp] = unpack2(a0);
        redb[kq][1][cp] = unpack2(a1);
        redb[kq][2][cp] = unpack2(a2);
        redb[kq][3][cp] = unpack2(a3);
        __syncthreads();                               // S1

        const int par = t & 1;
        if (kq == 0) {
            #pragma unroll
            for (int r = 0; r < 4; ++r) {
                const float2 o = redb[1][r][cp];
                ull tot = (r == 0 ? a0 : r == 1 ? a1 : r == 2 ? a2 : a3);
                tot = add2(tot, pack2(o.x, o.y));
                const float2 v = unpack2(tot);
                st_cluster_f2(mapa_peer(smem_u32(&zbuf[par][r][cp]), rank ^ 1u),
                              v.x, v.y);
            }
        }
        cluster_sync_();   // publishes zbuf pushes both directions

        // ---- finalize: column c = tid, 4 rows ----
        const int cpx = tid >> 1;
        const int comp = tid & 1;
        float z0, z1, z2, z3;
        {
            #pragma unroll
            for (int r = 0; r < 4; ++r) {
                const float2 ra = redb[0][r][cpx];
                const float2 rb = redb[1][r][cpx];
                const float2 zp = zbuf[par][r][cpx];
                const float own = comp ? (ra.y + rb.y) : (ra.x + rb.x);
                const float peer = comp ? zp.y : zp.x;
                const float zz = own + peer +
                    (r == 0 ? zx0 : r == 1 ? zx1 : r == 2 ? zx2 : zx3);
                if (r == 0) z0 = zz; else if (r == 1) z1 = zz;
                else if (r == 2) z2 = zz; else z3 = zz;
            }
        }
        if (rank == 0) {
            const float s = (z0 + z1) + (z2 + z3);
            const float q = (z0 * z0 + z1 * z1) + (z2 * z2 + z3 * z3);
            red_addf(&g_sum[t][tid], s);
            red_addf(&g_sq [t][tid], q);
        }
        __threadfence();                               // drain REDs to L2
        __syncthreads();                               // S2
        if (tid == 0) {
            if (rank == 0) atomicAdd(&g_cnt[0], 1u);
            const unsigned tgt = 64u * (unsigned)(t + 1);
            while (*vcnt < tgt) { }
            __threadfence();
        }
        __syncthreads();                               // S3

        const float sm = __ldcg(&g_sum[t][tid]);
        const float sq = __ldcg(&g_sq[t][tid]);
        const float mu  = sm * (1.f / 256.f);
        const float var = fmaf(-mu, mu, sq * (1.f / 256.f));
        const float ks  = rsqrtf(var + 1e-5f) * gam;
        const float h0 = gelu_f(fmaf(z0 - mu, ks, bet));
        const float h1 = gelu_f(fmaf(z1 - mu, ks, bet));
        const float h3v = gelu_f(fmaf(z3 - mu, ks, bet));
        const float h2v = gelu_f(fmaf(z2 - mu, ks, bet));

        if ((tid >> 7) == (int)rank) {
            const int kl = tid & 127;
            *(float4*)&h2[kl][0] = make_float4(h0, h0, h1, h1);
            *(float4*)&h2[kl][4] = make_float4(h2v, h2v, h3v, h3v);
        }
        if (rank == 0) {
            g_H[((size_t)t * 256 + b0 + 0) * 256 + tid] = h0;
            g_H[((size_t)t * 256 + b0 + 1) * 256 + tid] = h1;
            g_H[((size_t)t * 256 + b0 + 2) * 256 + tid] = h2v;
            g_H[((size_t)t * 256 + b0 + 3) * 256 + tid] = h3v;
        }
        __syncthreads();                               // S4: h2 ready
    }
}

// ---------------------------------------------------------------------------
// Kernel C: out[b,t,n] = gelu( sum_k H[t,b,k] * W_ho[n,k] + b_ho[n] )
// ---------------------------------------------------------------------------
__global__ void __launch_bounds__(256) proj_out_kernel(
    const float* __restrict__ W_ho, const float* __restrict__ b_ho,
    float* __restrict__ out)
{
    __shared__ float As[16][132];
    __shared__ float Bs[16][68];
    const int tid = threadIdx.x;
    const int r0  = blockIdx.x * 128;
    const int n0  = blockIdx.y * 64;
    const int t   = r0 >> 8;
    const int b0  = r0 & 255;
    const int tx  = tid & 15, ty = tid >> 4;

    float acc[8][4];
    #pragma unroll
    for (int i = 0; i < 8; ++i)
        #pragma unroll
        for (int j = 0; j < 4; ++j) acc[i][j] = 0.f;

    const int kq = (tid & 3) * 4;
    const int am = tid >> 2;

    for (int k0 = 0; k0 < H_SZ; k0 += 16) {
        #pragma unroll
        for (int h = 0; h < 2; ++h) {
            const int m = am + h * 64;
            const float4 v = *(const float4*)(g_H + (size_t)(r0 + m) * 256 + k0 + kq);
            As[kq + 0][m] = v.x; As[kq + 1][m] = v.y;
            As[kq + 2][m] = v.z; As[kq + 3][m] = v.w;
        }
        {
            const float4 v = *(const float4*)(W_ho + (size_t)(n0 + am) * H_SZ + k0 + kq);
            Bs[kq + 0][am] = v.x; Bs[kq + 1][am] = v.y;
            Bs[kq + 2][am] = v.z; Bs[kq + 3][am] = v.w;
        }
        __syncthreads();
        #pragma unroll
        for (int kk = 0; kk < 16; ++kk) {
            const float4 a0 = *(const float4*)&As[kk][ty * 8];
            const float4 a1 = *(const float4*)&As[kk][ty * 8 + 4];
            const float4 bv = *(const float4*)&Bs[kk][tx * 4];
            const float a[8] = {a0.x, a0.y, a0.z, a0.w, a1.x, a1.y, a1.z, a1.w};
            const float bb[4] = {bv.x, bv.y, bv.z, bv.w};
            #pragma unroll
            for (int i = 0; i < 8; ++i)
                #pragma unroll
                for (int j = 0; j < 4; ++j) acc[i][j] = fmaf(a[i], bb[j], acc[i][j]);
        }
        __syncthreads();
    }
    const float4 bv = *(const float4*)(b_ho + n0 + tx * 4);
    #pragma unroll
    for (int i = 0; i < 8; ++i) {
        float4 o;
        o.x = gelu_f(acc[i][0] + bv.x);
        o.y = gelu_f(acc[i][1] + bv.y);
        o.z = gelu_f(acc[i][2] + bv.z);
        o.w = gelu_f(acc[i][3] + bv.w);
        *(float4*)(out + (size_t)(b0 + ty * 8 + i) * (S_LEN * NO)
                   + (size_t)t * NO + n0 + tx * 4) = o;
    }
}

// ---------------------------------------------------------------------------
extern "C" void kernel_launch(void* const* d_in, const int* in_sizes, int n_in,
                              void* d_out, int out_size)
{
    const float* X     = (const float*)d_in[0];
    const float* W_ih  = (const float*)d_in[1];
    const float* b_ih  = (const float*)d_in[2];
    const float* W_ho  = (const float*)d_in[3];
    const float* b_ho  = (const float*)d_in[4];
    const float* gamma = (const float*)d_in[5];
    const float* beta  = (const float*)d_in[6];
    float* out = (float*)d_out;

    // Launch order places rec_kernel at launch #4 (the ncu-profiled slot).
    init_kernel<<<256, 256>>>();                                     // 1
    pad_kernel<<<1, 32>>>();                                         // 2
    proj_in_kernel<<<dim3((S_LEN * B_SZ) / 128, H_SZ / 64), 256>>>(  // 3
        X, W_ih, b_ih);
    rec_kernel<<<128, 256>>>(W_ih, gamma, beta);                     // 4
    proj_out_kernel<<<dim3((S_LEN * B_SZ) / 128, NO / 64), 256>>>(   // 5
        W_ho, b_ho, out);
}

// round 16
// speedup vs baseline: 1.4794x; 1.4794x over previous
#include <cuda_runtime.h>
#include <cuda_bf16.h>
#include <cstdint>

#define S_LEN 2048
#define B_SZ  256
#define H_SZ  256
#define NI    128
#define NO    128

typedef unsigned long long ull;

// Scratch (allocation-free)
__device__ float g_Zx[(size_t)S_LEN * B_SZ * H_SZ];   // (t, b, h)
__device__ float g_H [(size_t)S_LEN * B_SZ * H_SZ];   // (t, b, k)
__device__ float g_sum[S_LEN][H_SZ];                  // per-step BN sum (RED)
__device__ float g_sq [S_LEN][H_SZ];                  // per-step BN sumsq (RED)
__device__ unsigned g_cnt[32];                        // padded step counter

__device__ __forceinline__ float gelu_f(float x) {
    return 0.5f * x * (1.0f + erff(x * 0.70710678118654752440f));
}

// ---- packed f32x2 helpers (sm_103a) ----
__device__ __forceinline__ void fma2(ull& d, ull a, ull b) {
    asm("fma.rn.f32x2 %0, %1, %2, %3;" : "=l"(d) : "l"(a), "l"(b), "l"(d));
}
__device__ __forceinline__ ull add2(ull a, ull b) {
    ull r; asm("add.rn.f32x2 %0, %1, %2;" : "=l"(r) : "l"(a), "l"(b)); return r;
}
__device__ __forceinline__ ull pack2(float x, float y) {
    ull r; asm("mov.b64 %0, {%1, %2};" : "=l"(r) : "f"(x), "f"(y)); return r;
}
__device__ __forceinline__ float2 unpack2(ull v) {
    float2 f; asm("mov.b64 {%0, %1}, %2;" : "=f"(f.x), "=f"(f.y) : "l"(v)); return f;
}

// ---- cluster / sync helpers ----
__device__ __forceinline__ unsigned ctarank() {
    unsigned r; asm("mov.u32 %0, %%cluster_ctarank;" : "=r"(r)); return r;
}
__device__ __forceinline__ unsigned smem_u32(const void* p) {
    return (unsigned)__cvta_generic_to_shared(p);
}
__device__ __forceinline__ unsigned mapa_peer(unsigned laddr, unsigned rank) {
    unsigned r;
    asm("mapa.shared::cluster.u32 %0, %1, %2;" : "=r"(r) : "r"(laddr), "r"(rank));
    return r;
}
__device__ __forceinline__ void st_cluster_f2(unsigned addr, float x, float y) {
    asm volatile("st.shared::cluster.v2.f32 [%0], {%1, %2};"
                 :: "r"(addr), "f"(x), "f"(y) : "memory");
}
__device__ __forceinline__ void cluster_sync_() {
    asm volatile("barrier.cluster.arrive.aligned;" ::: "memory");
    asm volatile("barrier.cluster.wait.aligned;" ::: "memory");
}
__device__ __forceinline__ void red_addf(float* p, float v) {
    asm volatile("red.global.add.f32 [%0], %1;" :: "l"(p), "f"(v) : "memory");
}

// ---- bf16 split helpers ----
__device__ __forceinline__ unsigned pack_bf16(float x, float y) {
    __nv_bfloat162 h = __floats2bfloat162_rn(x, y);
    return *(unsigned*)&h;
}

// mma.sync m16n8k16 bf16 (base sm_80+ PTX feature; legal on compute_103)
__device__ __forceinline__ void mma_bf16(float* c, const unsigned* a,
                                         unsigned b0, unsigned b1) {
    asm volatile(
        "mma.sync.aligned.m16n8k16.row.col.f32.bf16.bf16.f32 "
        "{%0,%1,%2,%3}, {%4,%5,%6,%7}, {%8,%9}, {%0,%1,%2,%3};"
        : "+f"(c[0]), "+f"(c[1]), "+f"(c[2]), "+f"(c[3])
        : "r"(a[0]), "r"(a[1]), "r"(a[2]), "r"(a[3]), "r"(b0), "r"(b1));
}

__global__ void init_kernel() {
    const size_t n = (size_t)S_LEN * H_SZ;
    const size_t stride = (size_t)gridDim.x * blockDim.x;
    for (size_t i = (size_t)blockIdx.x * blockDim.x + threadIdx.x; i < n; i += stride) {
        ((float*)g_sum)[i] = 0.f;
        ((float*)g_sq)[i]  = 0.f;
    }
    if (blockIdx.x == 0 && threadIdx.x < 32) g_cnt[threadIdx.x] = 0u;
}

// ---------------------------------------------------------------------------
// Kernel A: Zx[t,b,n] = sum_i X[b,t,i] * W_ih[n,i] + b_ih[n]  (champion)
// ---------------------------------------------------------------------------
__global__ void __launch_bounds__(256) proj_in_kernel(
    const float* __restrict__ X, const float* __restrict__ W_ih,
    const float* __restrict__ b_ih)
{
    __shared__ float As[16][132];
    __shared__ float Bs[16][68];
    const int tid = threadIdx.x;
    const int r0  = blockIdx.x * 128;
    const int n0  = blockIdx.y * 64;
    const int t   = r0 >> 8;
    const int b0  = r0 & 255;
    const int tx  = tid & 15, ty = tid >> 4;

    float acc[8][4];
    #pragma unroll
    for (int i = 0; i < 8; ++i)
        #pragma unroll
        for (int j = 0; j < 4; ++j) acc[i][j] = 0.f;

    const int kq = (tid & 3) * 4;
    const int am = tid >> 2;

    for (int k0 = 0; k0 < NI; k0 += 16) {
        #pragma unroll
        for (int h = 0; h < 2; ++h) {
            const int m = am + h * 64;
            const float4 v = *(const float4*)(X + (size_t)(b0 + m) * (S_LEN * NI)
                                              + (size_t)t * NI + k0 + kq);
            As[kq + 0][m] = v.x; As[kq + 1][m] = v.y;
            As[kq + 2][m] = v.z; As[kq + 3][m] = v.w;
        }
        {
            const float4 v = *(const float4*)(W_ih + (size_t)(n0 + am) * 384 + k0 + kq);
            Bs[kq + 0][am] = v.x; Bs[kq + 1][am] = v.y;
            Bs[kq + 2][am] = v.z; Bs[kq + 3][am] = v.w;
        }
        __syncthreads();
        #pragma unroll
        for (int kk = 0; kk < 16; ++kk) {
            const float4 a0 = *(const float4*)&As[kk][ty * 8];
            const float4 a1 = *(const float4*)&As[kk][ty * 8 + 4];
            const float4 bv = *(const float4*)&Bs[kk][tx * 4];
            const float a[8] = {a0.x, a0.y, a0.z, a0.w, a1.x, a1.y, a1.z, a1.w};
            const float bb[4] = {bv.x, bv.y, bv.z, bv.w};
            #pragma unroll
            for (int i = 0; i < 8; ++i)
                #pragma unroll
                for (int j = 0; j < 4; ++j) acc[i][j] = fmaf(a[i], bb[j], acc[i][j]);
        }
        __syncthreads();
    }
    const float4 bv = *(const float4*)(b_ih + n0 + tx * 4);
    #pragma unroll
    for (int i = 0; i < 8; ++i) {
        float4 o;
        o.x = acc[i][0] + bv.x; o.y = acc[i][1] + bv.y;
        o.z = acc[i][2] + bv.z; o.w = acc[i][3] + bv.w;
        *(float4*)(g_Zx + (size_t)(r0 + ty * 8 + i) * 256 + n0 + tx * 4) = o;
    }
}

// ---------------------------------------------------------------------------
// Kernel B: champion rec (R6 k-split + 256-thread finalize). Unchanged.
// ---------------------------------------------------------------------------
__global__ void __launch_bounds__(256, 1) __cluster_dims__(2, 1, 1)
rec_kernel(const float* __restrict__ W_ih, const float* __restrict__ gamma,
           const float* __restrict__ beta)
{
    __shared__ float  h2[128][8];
    __shared__ float2 redb[2][4][128];
    __shared__ float2 zbuf[2][4][128];

    const int tid  = threadIdx.x;
    const unsigned rank = ctarank();
    const int b0   = (blockIdx.x >> 1) * 4;
    const int kq   = tid >> 7;
    const int cp   = tid & 127;
    const int c2   = cp * 2;

    ull wreg[64];
    {
        const int kbase = NI + (int)rank * 128 + kq * 64;
        const float* w0p = W_ih + (size_t)c2 * 384 + kbase;
        const float* w1p = W_ih + (size_t)(c2 + 1) * 384 + kbase;
        #pragma unroll
        for (int i = 0; i < 64; ++i) wreg[i] = pack2(w0p[i], w1p[i]);
    }
    const float gam = gamma[tid];
    const float bet = beta[tid];

    volatile unsigned* vcnt = (volatile unsigned*)&g_cnt[0];

    for (int t = 0; t < S_LEN; ++t) {
        float zx0 = __ldcg(g_Zx + ((size_t)t * 256 + b0 + 0) * 256 + tid);
        float zx1 = __ldcg(g_Zx + ((size_t)t * 256 + b0 + 1) * 256 + tid);
        float zx2 = __ldcg(g_Zx + ((size_t)t * 256 + b0 + 2) * 256 + tid);
        float zx3 = __ldcg(g_Zx + ((size_t)t * 256 + b0 + 3) * 256 + tid);

        ull a0 = 0ull, a1 = 0ull, a2 = 0ull, a3 = 0ull;
        if (t > 0) {
            const int kb = kq * 64;
            #pragma unroll
            for (int i = 0; i < 64; ++i) {
                const ulonglong2 p01 = *(const ulonglong2*)&h2[kb + i][0];
                const ulonglong2 p23 = *(const ulonglong2*)&h2[kb + i][4];
                fma2(a0, p01.x, wreg[i]);
                fma2(a1, p01.y, wreg[i]);
                fma2(a2, p23.x, wreg[i]);
                fma2(a3, p23.y, wreg[i]);
            }
        }
        redb[kq][0][cp] = unpack2(a0);
        redb[kq][1][cp] = unpack2(a1);
        redb[kq][2][cp] = unpack2(a2);
        redb[kq][3][cp] = unpack2(a3);
        __syncthreads();

        const int par = t & 1;
        if (kq == 0) {
            #pragma unroll
            for (int r = 0; r < 4; ++r) {
                const float2 o = redb[1][r][cp];
                ull tot = (r == 0 ? a0 : r == 1 ? a1 : r == 2 ? a2 : a3);
                tot = add2(tot, pack2(o.x, o.y));
                const float2 v = unpack2(tot);
                st_cluster_f2(mapa_peer(smem_u32(&zbuf[par][r][cp]), rank ^ 1u),
                              v.x, v.y);
            }
        }
        cluster_sync_();

        const int cpx = tid >> 1;
        const int comp = tid & 1;
        float z0, z1, z2, z3;
        {
            #pragma unroll
            for (int r = 0; r < 4; ++r) {
                const float2 ra = redb[0][r][cpx];
                const float2 rb = redb[1][r][cpx];
                const float2 zp = zbuf[par][r][cpx];
                const float own = comp ? (ra.y + rb.y) : (ra.x + rb.x);
                const float peer = comp ? zp.y : zp.x;
                const float zz = own + peer +
                    (r == 0 ? zx0 : r == 1 ? zx1 : r == 2 ? zx2 : zx3);
                if (r == 0) z0 = zz; else if (r == 1) z1 = zz;
                else if (r == 2) z2 = zz; else z3 = zz;
            }
        }
        if (rank == 0) {
            const float s = (z0 + z1) + (z2 + z3);
            const float q = (z0 * z0 + z1 * z1) + (z2 * z2 + z3 * z3);
            red_addf(&g_sum[t][tid], s);
            red_addf(&g_sq [t][tid], q);
        }
        __threadfence();
        __syncthreads();
        if (tid == 0) {
            if (rank == 0) atomicAdd(&g_cnt[0], 1u);
            const unsigned tgt = 64u * (unsigned)(t + 1);
            while (*vcnt < tgt) { }
            __threadfence();
        }
        __syncthreads();

        const float sm = __ldcg(&g_sum[t][tid]);
        const float sq = __ldcg(&g_sq[t][tid]);
        const float mu  = sm * (1.f / 256.f);
        const float var = fmaf(-mu, mu, sq * (1.f / 256.f));
        const float ks  = rsqrtf(var + 1e-5f) * gam;
        const float h0 = gelu_f(fmaf(z0 - mu, ks, bet));
        const float h1 = gelu_f(fmaf(z1 - mu, ks, bet));
        const float h3v = gelu_f(fmaf(z3 - mu, ks, bet));
        const float h2v = gelu_f(fmaf(z2 - mu, ks, bet));

        if ((tid >> 7) == (int)rank) {
            const int kl = tid & 127;
            *(float4*)&h2[kl][0] = make_float4(h0, h0, h1, h1);
            *(float4*)&h2[kl][4] = make_float4(h2v, h2v, h3v, h3v);
        }
        if (rank == 0) {
            g_H[((size_t)t * 256 + b0 + 0) * 256 + tid] = h0;
            g_H[((size_t)t * 256 + b0 + 1) * 256 + tid] = h1;
            g_H[((size_t)t * 256 + b0 + 2) * 256 + tid] = h2v;
            g_H[((size_t)t * 256 + b0 + 3) * 256 + tid] = h3v;
        }
        __syncthreads();
    }
}

// ---------------------------------------------------------------------------
// Kernel C: out = gelu(H @ W_ho^T + b_ho) via mma.sync bf16 3-term split.
// Tile M=128 x N=128 x K=256 (8 chunks of 32). 256 threads = 8 warps,
// warp tile 32x64. A = g_H rows (k-contig, .row); B = W_ho rows (k-contig,
// .col). hi/lo bf16 split: acc += Ahi*Bhi + Ahi*Blo + Alo*Bhi (err ~2^-16).
// ---------------------------------------------------------------------------
__global__ void __launch_bounds__(256) proj_out_mma(
    const float* __restrict__ W_ho, const float* __restrict__ b_ho,
    float* __restrict__ out)
{
    __shared__ unsigned Ah[128][17], Al[128][17];   // packed bf16 pairs
    __shared__ unsigned Bh[128][17], Bl[128][17];
    __shared__ float bs[128];

    const int tid  = threadIdx.x;
    const int wid  = tid >> 5, lane = tid & 31;
    const int r0   = blockIdx.x * 128;
    const int t    = r0 >> 8;
    const int b0   = r0 & 255;

    if (tid < 128) bs[tid] = b_ho[tid];

    float acc[2][8][4];
    #pragma unroll
    for (int mt = 0; mt < 2; ++mt)
        #pragma unroll
        for (int nt = 0; nt < 8; ++nt)
            #pragma unroll
            for (int q = 0; q < 4; ++q) acc[mt][nt][q] = 0.f;

    // staging role: row = tid>>1 (A row / B n), half = tid&1 (pairs 8..15 / 0..7)
    const int srow = tid >> 1, shf = tid & 1;
    const float2* asrc = (const float2*)(g_H + ((size_t)t * 256 + b0 + srow) * 256);
    const float2* bsrc = (const float2*)(W_ho + (size_t)srow * H_SZ);

    // mma role
    const int g  = lane >> 2, tq = lane & 3;
    const int wm = (wid & 3) * 32;
    const int wn = (wid >> 2) * 64;

    for (int kc = 0; kc < 8; ++kc) {
        __syncthreads();   // WAR: prior iter's frag reads done before overwrite
        #pragma unroll
        for (int j = 0; j < 8; ++j) {
            const int p = shf * 8 + j;
            {
                const float2 v = asrc[kc * 16 + p];
                const unsigned hi = pack_bf16(v.x, v.y);
                const __nv_bfloat162 hb = *(const __nv_bfloat162*)&hi;
                Ah[srow][p] = hi;
                Al[srow][p] = pack_bf16(v.x - __low2float(hb),
                                        v.y - __high2float(hb));
            }
            {
                const float2 v = bsrc[kc * 16 + p];
                const unsigned hi = pack_bf16(v.x, v.y);
                const __nv_bfloat162 hb = *(const __nv_bfloat162*)&hi;
                Bh[srow][p] = hi;
                Bl[srow][p] = pack_bf16(v.x - __low2float(hb),
                                        v.y - __high2float(hb));
            }
        }
        __syncthreads();

        #pragma unroll
        for (int kk = 0; kk < 2; ++kk) {
            const int p0 = kk * 8 + tq, p1 = p0 + 4;
            unsigned ah[2][4], al[2][4];
            #pragma unroll
            for (int mt = 0; mt < 2; ++mt) {
                const int r = wm + mt * 16 + g;
                ah[mt][0] = Ah[r][p0];     ah[mt][1] = Ah[r + 8][p0];
                ah[mt][2] = Ah[r][p1];     ah[mt][3] = Ah[r + 8][p1];
                al[mt][0] = Al[r][p0];     al[mt][1] = Al[r + 8][p0];
                al[mt][2] = Al[r][p1];     al[mt][3] = Al[r + 8][p1];
            }
            #pragma unroll
            for (int nt = 0; nt < 8; ++nt) {
                const int n = wn + nt * 8 + g;
                const unsigned bh0 = Bh[n][p0], bh1 = Bh[n][p1];
                const unsigned bl0 = Bl[n][p0], bl1 = Bl[n][p1];
                #pragma unroll
                for (int mt = 0; mt < 2; ++mt) {
                    mma_bf16(acc[mt][nt], ah[mt], bh0, bh1);
                    mma_bf16(acc[mt][nt], ah[mt], bl0, bl1);
                    mma_bf16(acc[mt][nt], al[mt], bh0, bh1);
                }
            }
        }
    }

    // epilogue: d0,d1 = row g / cols 2tq,2tq+1 ; d2,d3 = row g+8
    #pragma unroll
    for (int mt = 0; mt < 2; ++mt) {
        #pragma unroll
        for (int nt = 0; nt < 8; ++nt) {
            const int c0 = wn + nt * 8 + tq * 2;
            const float bv0 = bs[c0], bv1 = bs[c0 + 1];
            const int rA = wm + mt * 16 + g;
            float* pA = out + (size_t)(b0 + rA) * (S_LEN * NO) + (size_t)t * NO + c0;
            float* pB = out + (size_t)(b0 + rA + 8) * (S_LEN * NO) + (size_t)t * NO + c0;
            float2 oA, oB;
            oA.x = gelu_f(acc[mt][nt][0] + bv0);
            oA.y = gelu_f(acc[mt][nt][1] + bv1);
            oB.x = gelu_f(acc[mt][nt][2] + bv0);
            oB.y = gelu_f(acc[mt][nt][3] + bv1);
            *(float2*)pA = oA;
            *(float2*)pB = oB;
        }
    }
}

// ---------------------------------------------------------------------------
extern "C" void kernel_launch(void* const* d_in, const int* in_sizes, int n_in,
                              void* d_out, int out_size)
{
    const float* X     = (const float*)d_in[0];
    const float* W_ih  = (const float*)d_in[1];
    const float* b_ih  = (const float*)d_in[2];
    const float* W_ho  = (const float*)d_in[3];
    const float* b_ho  = (const float*)d_in[4];
    const float* gamma = (const float*)d_in[5];
    const float* beta  = (const float*)d_in[6];
    float* out = (float*)d_out;

    init_kernel<<<256, 256>>>();
    proj_in_kernel<<<dim3((S_LEN * B_SZ) / 128, H_SZ / 64), 256>>>(X, W_ih, b_ih);
    rec_kernel<<<128, 256>>>(W_ih, gamma, beta);
    proj_out_mma<<<(S_LEN * B_SZ) / 128, 256>>>(W_ho, b_ho, out);
}

// round 17
// speedup vs baseline: 1.5090x; 1.0200x over previous
#include <cuda_runtime.h>
#include <cuda_bf16.h>
#include <cstdint>

#define S_LEN 2048
#define B_SZ  256
#define H_SZ  256
#define NI    128
#define NO    128

typedef unsigned long long ull;

// Scratch (allocation-free)
__device__ float g_Zx[(size_t)S_LEN * B_SZ * H_SZ];   // (t, b, h)
__device__ float g_H [(size_t)S_LEN * B_SZ * H_SZ];   // (t, b, k)
__device__ float g_sum[S_LEN][H_SZ];                  // per-step BN sum (RED)
__device__ float g_sq [S_LEN][H_SZ];                  // per-step BN sumsq (RED)
__device__ unsigned g_cnt[32];                        // padded step counter

__device__ __forceinline__ float gelu_f(float x) {
    return 0.5f * x * (1.0f + erff(x * 0.70710678118654752440f));
}

// ---- packed f32x2 helpers (sm_103a) ----
__device__ __forceinline__ void fma2(ull& d, ull a, ull b) {
    asm("fma.rn.f32x2 %0, %1, %2, %3;" : "=l"(d) : "l"(a), "l"(b), "l"(d));
}
__device__ __forceinline__ ull add2(ull a, ull b) {
    ull r; asm("add.rn.f32x2 %0, %1, %2;" : "=l"(r) : "l"(a), "l"(b)); return r;
}
__device__ __forceinline__ ull pack2(float x, float y) {
    ull r; asm("mov.b64 %0, {%1, %2};" : "=l"(r) : "f"(x), "f"(y)); return r;
}
__device__ __forceinline__ float2 unpack2(ull v) {
    float2 f; asm("mov.b64 {%0, %1}, %2;" : "=f"(f.x), "=f"(f.y) : "l"(v)); return f;
}

// ---- cluster / sync helpers ----
__device__ __forceinline__ unsigned ctarank() {
    unsigned r; asm("mov.u32 %0, %%cluster_ctarank;" : "=r"(r)); return r;
}
__device__ __forceinline__ unsigned smem_u32(const void* p) {
    return (unsigned)__cvta_generic_to_shared(p);
}
__device__ __forceinline__ unsigned mapa_peer(unsigned laddr, unsigned rank) {
    unsigned r;
    asm("mapa.shared::cluster.u32 %0, %1, %2;" : "=r"(r) : "r"(laddr), "r"(rank));
    return r;
}
__device__ __forceinline__ void st_cluster_f2(unsigned addr, float x, float y) {
    asm volatile("st.shared::cluster.v2.f32 [%0], {%1, %2};"
                 :: "r"(addr), "f"(x), "f"(y) : "memory");
}
__device__ __forceinline__ void cluster_sync_() {
    asm volatile("barrier.cluster.arrive.aligned;" ::: "memory");
    asm volatile("barrier.cluster.wait.aligned;" ::: "memory");
}
__device__ __forceinline__ void red_addf(float* p, float v) {
    asm volatile("red.global.add.f32 [%0], %1;" :: "l"(p), "f"(v) : "memory");
}

// ---- bf16 split helpers ----
__device__ __forceinline__ unsigned pack_bf16(float x, float y) {
    __nv_bfloat162 h = __floats2bfloat162_rn(x, y);
    return *(unsigned*)&h;
}

// mma.sync m16n8k16 bf16 (base sm_80+ PTX feature; legal on compute_103)
__device__ __forceinline__ void mma_bf16(float* c, const unsigned* a,
                                         unsigned b0, unsigned b1) {
    asm volatile(
        "mma.sync.aligned.m16n8k16.row.col.f32.bf16.bf16.f32 "
        "{%0,%1,%2,%3}, {%4,%5,%6,%7}, {%8,%9}, {%0,%1,%2,%3};"
        : "+f"(c[0]), "+f"(c[1]), "+f"(c[2]), "+f"(c[3])
        : "r"(a[0]), "r"(a[1]), "r"(a[2]), "r"(a[3]), "r"(b0), "r"(b1));
}

__global__ void init_kernel() {
    const size_t n = (size_t)S_LEN * H_SZ;
    const size_t stride = (size_t)gridDim.x * blockDim.x;
    for (size_t i = (size_t)blockIdx.x * blockDim.x + threadIdx.x; i < n; i += stride) {
        ((float*)g_sum)[i] = 0.f;
        ((float*)g_sq)[i]  = 0.f;
    }
    if (blockIdx.x == 0 && threadIdx.x < 32) g_cnt[threadIdx.x] = 0u;
}

// ---------------------------------------------------------------------------
// Kernel A: Zx = X @ W_x^T + b_ih via mma.sync bf16 3-term split.
// GEMM M=S*B, N=256 (2 grid.y halves of 128), K=128 (4 chunks of 32).
// A row (b0+srow, t) of X is k-contiguous; B row = W_ih[n0+srow][0:128].
// Same fragment maps as proj_out_mma (validated R16).
// ---------------------------------------------------------------------------
__global__ void __launch_bounds__(256) proj_in_mma(
    const float* __restrict__ X, const float* __restrict__ W_ih,
    const float* __restrict__ b_ih)
{
    __shared__ unsigned Ah[128][17], Al[128][17];
    __shared__ unsigned Bh[128][17], Bl[128][17];
    __shared__ float bs[128];

    const int tid  = threadIdx.x;
    const int wid  = tid >> 5, lane = tid & 31;
    const int r0   = blockIdx.x * 128;
    const int n0   = blockIdx.y * 128;
    const int t    = r0 >> 8;
    const int b0   = r0 & 255;

    if (tid < 128) bs[tid] = b_ih[n0 + tid];

    float acc[2][8][4];
    #pragma unroll
    for (int mt = 0; mt < 2; ++mt)
        #pragma unroll
        for (int nt = 0; nt < 8; ++nt)
            #pragma unroll
            for (int q = 0; q < 4; ++q) acc[mt][nt][q] = 0.f;

    const int srow = tid >> 1, shf = tid & 1;
    const float2* asrc = (const float2*)(X + (size_t)(b0 + srow) * (S_LEN * NI)
                                         + (size_t)t * NI);
    const float2* bsrc = (const float2*)(W_ih + (size_t)(n0 + srow) * 384);

    const int g  = lane >> 2, tq = lane & 3;
    const int wm = (wid & 3) * 32;
    const int wn = (wid >> 2) * 64;

    for (int kc = 0; kc < 4; ++kc) {
        __syncthreads();
        #pragma unroll
        for (int j = 0; j < 8; ++j) {
            const int p = shf * 8 + j;
            {
                const float2 v = asrc[kc * 16 + p];
                const unsigned hi = pack_bf16(v.x, v.y);
                const __nv_bfloat162 hb = *(const __nv_bfloat162*)&hi;
                Ah[srow][p] = hi;
                Al[srow][p] = pack_bf16(v.x - __low2float(hb),
                                        v.y - __high2float(hb));
            }
            {
                const float2 v = bsrc[kc * 16 + p];
                const unsigned hi = pack_bf16(v.x, v.y);
                const __nv_bfloat162 hb = *(const __nv_bfloat162*)&hi;
                Bh[srow][p] = hi;
                Bl[srow][p] = pack_bf16(v.x - __low2float(hb),
                                        v.y - __high2float(hb));
            }
        }
        __syncthreads();

        #pragma unroll
        for (int kk = 0; kk < 2; ++kk) {
            const int p0 = kk * 8 + tq, p1 = p0 + 4;
            unsigned ah[2][4], al[2][4];
            #pragma unroll
            for (int mt = 0; mt < 2; ++mt) {
                const int r = wm + mt * 16 + g;
                ah[mt][0] = Ah[r][p0];     ah[mt][1] = Ah[r + 8][p0];
                ah[mt][2] = Ah[r][p1];     ah[mt][3] = Ah[r + 8][p1];
                al[mt][0] = Al[r][p0];     al[mt][1] = Al[r + 8][p0];
                al[mt][2] = Al[r][p1];     al[mt][3] = Al[r + 8][p1];
            }
            #pragma unroll
            for (int nt = 0; nt < 8; ++nt) {
                const int n = wn + nt * 8 + g;
                const unsigned bh0 = Bh[n][p0], bh1 = Bh[n][p1];
                const unsigned bl0 = Bl[n][p0], bl1 = Bl[n][p1];
                #pragma unroll
                for (int mt = 0; mt < 2; ++mt) {
                    mma_bf16(acc[mt][nt], ah[mt], bh0, bh1);
                    mma_bf16(acc[mt][nt], ah[mt], bl0, bl1);
                    mma_bf16(acc[mt][nt], al[mt], bh0, bh1);
                }
            }
        }
    }

    #pragma unroll
    for (int mt = 0; mt < 2; ++mt) {
        #pragma unroll
        for (int nt = 0; nt < 8; ++nt) {
            const int cl = wn + nt * 8 + tq * 2;
            const float bv0 = bs[cl], bv1 = bs[cl + 1];
            const int rA = wm + mt * 16 + g;
            float* pA = g_Zx + ((size_t)t * 256 + b0 + rA) * 256 + n0 + cl;
            float* pB = g_Zx + ((size_t)t * 256 + b0 + rA + 8) * 256 + n0 + cl;
            *(float2*)pA = make_float2(acc[mt][nt][0] + bv0, acc[mt][nt][1] + bv1);
            *(float2*)pB = make_float2(acc[mt][nt][2] + bv0, acc[mt][nt][3] + bv1);
        }
    }
}

// ---------------------------------------------------------------------------
// Kernel B: champion rec (R6 k-split + 256-thread finalize). Unchanged.
// ---------------------------------------------------------------------------
__global__ void __launch_bounds__(256, 1) __cluster_dims__(2, 1, 1)
rec_kernel(const float* __restrict__ W_ih, const float* __restrict__ gamma,
           const float* __restrict__ beta)
{
    __shared__ float  h2[128][8];
    __shared__ float2 redb[2][4][128];
    __shared__ float2 zbuf[2][4][128];

    const int tid  = threadIdx.x;
    const unsigned rank = ctarank();
    const int b0   = (blockIdx.x >> 1) * 4;
    const int kq   = tid >> 7;
    const int cp   = tid & 127;
    const int c2   = cp * 2;

    ull wreg[64];
    {
        const int kbase = NI + (int)rank * 128 + kq * 64;
        const float* w0p = W_ih + (size_t)c2 * 384 + kbase;
        const float* w1p = W_ih + (size_t)(c2 + 1) * 384 + kbase;
        #pragma unroll
        for (int i = 0; i < 64; ++i) wreg[i] = pack2(w0p[i], w1p[i]);
    }
    const float gam = gamma[tid];
    const float bet = beta[tid];

    volatile unsigned* vcnt = (volatile unsigned*)&g_cnt[0];

    for (int t = 0; t < S_LEN; ++t) {
        float zx0 = __ldcg(g_Zx + ((size_t)t * 256 + b0 + 0) * 256 + tid);
        float zx1 = __ldcg(g_Zx + ((size_t)t * 256 + b0 + 1) * 256 + tid);
        float zx2 = __ldcg(g_Zx + ((size_t)t * 256 + b0 + 2) * 256 + tid);
        float zx3 = __ldcg(g_Zx + ((size_t)t * 256 + b0 + 3) * 256 + tid);

        ull a0 = 0ull, a1 = 0ull, a2 = 0ull, a3 = 0ull;
        if (t > 0) {
            const int kb = kq * 64;
            #pragma unroll
            for (int i = 0; i < 64; ++i) {
                const ulonglong2 p01 = *(const ulonglong2*)&h2[kb + i][0];
                const ulonglong2 p23 = *(const ulonglong2*)&h2[kb + i][4];
                fma2(a0, p01.x, wreg[i]);
                fma2(a1, p01.y, wreg[i]);
                fma2(a2, p23.x, wreg[i]);
                fma2(a3, p23.y, wreg[i]);
            }
        }
        redb[kq][0][cp] = unpack2(a0);
        redb[kq][1][cp] = unpack2(a1);
        redb[kq][2][cp] = unpack2(a2);
        redb[kq][3][cp] = unpack2(a3);
        __syncthreads();

        const int par = t & 1;
        if (kq == 0) {
            #pragma unroll
            for (int r = 0; r < 4; ++r) {
                const float2 o = redb[1][r][cp];
                ull tot = (r == 0 ? a0 : r == 1 ? a1 : r == 2 ? a2 : a3);
                tot = add2(tot, pack2(o.x, o.y));
                const float2 v = unpack2(tot);
                st_cluster_f2(mapa_peer(smem_u32(&zbuf[par][r][cp]), rank ^ 1u),
                              v.x, v.y);
            }
        }
        cluster_sync_();

        const int cpx = tid >> 1;
        const int comp = tid & 1;
        float z0, z1, z2, z3;
        {
            #pragma unroll
            for (int r = 0; r < 4; ++r) {
                const float2 ra = redb[0][r][cpx];
                const float2 rb = redb[1][r][cpx];
                const float2 zp = zbuf[par][r][cpx];
                const float own = comp ? (ra.y + rb.y) : (ra.x + rb.x);
                const float peer = comp ? zp.y : zp.x;
                const float zz = own + peer +
                    (r == 0 ? zx0 : r == 1 ? zx1 : r == 2 ? zx2 : zx3);
                if (r == 0) z0 = zz; else if (r == 1) z1 = zz;
                else if (r == 2) z2 = zz; else z3 = zz;
            }
        }
        if (rank == 0) {
            const float s = (z0 + z1) + (z2 + z3);
            const float q = (z0 * z0 + z1 * z1) + (z2 * z2 + z3 * z3);
            red_addf(&g_sum[t][tid], s);
            red_addf(&g_sq [t][tid], q);
        }
        __threadfence();
        __syncthreads();
        if (tid == 0) {
            if (rank == 0) atomicAdd(&g_cnt[0], 1u);
            const unsigned tgt = 64u * (unsigned)(t + 1);
            while (*vcnt < tgt) { }
            __threadfence();
        }
        __syncthreads();

        const float sm = __ldcg(&g_sum[t][tid]);
        const float sq = __ldcg(&g_sq[t][tid]);
        const float mu  = sm * (1.f / 256.f);
        const float var = fmaf(-mu, mu, sq * (1.f / 256.f));
        const float ks  = rsqrtf(var + 1e-5f) * gam;
        const float h0 = gelu_f(fmaf(z0 - mu, ks, bet));
        const float h1 = gelu_f(fmaf(z1 - mu, ks, bet));
        const float h3v = gelu_f(fmaf(z3 - mu, ks, bet));
        const float h2v = gelu_f(fmaf(z2 - mu, ks, bet));

        if ((tid >> 7) == (int)rank) {
            const int kl = tid & 127;
            *(float4*)&h2[kl][0] = make_float4(h0, h0, h1, h1);
            *(float4*)&h2[kl][4] = make_float4(h2v, h2v, h3v, h3v);
        }
        if (rank == 0) {
            g_H[((size_t)t * 256 + b0 + 0) * 256 + tid] = h0;
            g_H[((size_t)t * 256 + b0 + 1) * 256 + tid] = h1;
            g_H[((size_t)t * 256 + b0 + 2) * 256 + tid] = h2v;
            g_H[((size_t)t * 256 + b0 + 3) * 256 + tid] = h3v;
        }
        __syncthreads();
    }
}

// ---------------------------------------------------------------------------
// Kernel C: out = gelu(H @ W_ho^T + b_ho) via mma.sync bf16 3-term split.
// (Unchanged from R16: validated at rel_err 4.9e-6.)
// ---------------------------------------------------------------------------
__global__ void __launch_bounds__(256) proj_out_mma(
    const float* __restrict__ W_ho, const float* __restrict__ b_ho,
    float* __restrict__ out)
{
    __shared__ unsigned Ah[128][17], Al[128][17];
    __shared__ unsigned Bh[128][17], Bl[128][17];
    __shared__ float bs[128];

    const int tid  = threadIdx.x;
    const int wid  = tid >> 5, lane = tid & 31;
    const int r0   = blockIdx.x * 128;
    const int t    = r0 >> 8;
    const int b0   = r0 & 255;

    if (tid < 128) bs[tid] = b_ho[tid];

    float acc[2][8][4];
    #pragma unroll
    for (int mt = 0; mt < 2; ++mt)
        #pragma unroll
        for (int nt = 0; nt < 8; ++nt)
            #pragma unroll
            for (int q = 0; q < 4; ++q) acc[mt][nt][q] = 0.f;

    const int srow = tid >> 1, shf = tid & 1;
    const float2* asrc = (const float2*)(g_H + ((size_t)t * 256 + b0 + srow) * 256);
    const float2* bsrc = (const float2*)(W_ho + (size_t)srow * H_SZ);

    const int g  = lane >> 2, tq = lane & 3;
    const int wm = (wid & 3) * 32;
    const int wn = (wid >> 2) * 64;

    for (int kc = 0; kc < 8; ++kc) {
        __syncthreads();
        #pragma unroll
        for (int j = 0; j < 8; ++j) {
            const int p = shf * 8 + j;
            {
                const float2 v = asrc[kc * 16 + p];
                const unsigned hi = pack_bf16(v.x, v.y);
                const __nv_bfloat162 hb = *(const __nv_bfloat162*)&hi;
                Ah[srow][p] = hi;
                Al[srow][p] = pack_bf16(v.x - __low2float(hb),
                                        v.y - __high2float(hb));
            }
            {
                const float2 v = bsrc[kc * 16 + p];
                const unsigned hi = pack_bf16(v.x, v.y);
                const __nv_bfloat162 hb = *(const __nv_bfloat162*)&hi;
                Bh[srow][p] = hi;
                Bl[srow][p] = pack_bf16(v.x - __low2float(hb),
                                        v.y - __high2float(hb));
            }
        }
        __syncthreads();

        #pragma unroll
        for (int kk = 0; kk < 2; ++kk) {
            const int p0 = kk * 8 + tq, p1 = p0 + 4;
            unsigned ah[2][4], al[2][4];
            #pragma unroll
            for (int mt = 0; mt < 2; ++mt) {
                const int r = wm + mt * 16 + g;
                ah[mt][0] = Ah[r][p0];     ah[mt][1] = Ah[r + 8][p0];
                ah[mt][2] = Ah[r][p1];     ah[mt][3] = Ah[r + 8][p1];
                al[mt][0] = Al[r][p0];     al[mt][1] = Al[r + 8][p0];
                al[mt][2] = Al[r][p1];     al[mt][3] = Al[r + 8][p1];
            }
            #pragma unroll
            for (int nt = 0; nt < 8; ++nt) {
                const int n = wn + nt * 8 + g;
                const unsigned bh0 = Bh[n][p0], bh1 = Bh[n][p1];
                const unsigned bl0 = Bl[n][p0], bl1 = Bl[n][p1];
                #pragma unroll
                for (int mt = 0; mt < 2; ++mt) {
                    mma_bf16(acc[mt][nt], ah[mt], bh0, bh1);
                    mma_bf16(acc[mt][nt], ah[mt], bl0, bl1);
                    mma_bf16(acc[mt][nt], al[mt], bh0, bh1);
                }
            }
        }
    }

    #pragma unroll
    for (int mt = 0; mt < 2; ++mt) {
        #pragma unroll
        for (int nt = 0; nt < 8; ++nt) {
            const int c0 = wn + nt * 8 + tq * 2;
            const float bv0 = bs[c0], bv1 = bs[c0 + 1];
            const int rA = wm + mt * 16 + g;
            float* pA = out + (size_t)(b0 + rA) * (S_LEN * NO) + (size_t)t * NO + c0;
            float* pB = out + (size_t)(b0 + rA + 8) * (S_LEN * NO) + (size_t)t * NO + c0;
            float2 oA, oB;
            oA.x = gelu_f(acc[mt][nt][0] + bv0);
            oA.y = gelu_f(acc[mt][nt][1] + bv1);
            oB.x = gelu_f(acc[mt][nt][2] + bv0);
            oB.y = gelu_f(acc[mt][nt][3] + bv1);
            *(float2*)pA = oA;
            *(float2*)pB = oB;
        }
    }
}

// ---------------------------------------------------------------------------
extern "C" void kernel_launch(void* const* d_in, const int* in_sizes, int n_in,
                              void* d_out, int out_size)
{
    const float* X     = (const float*)d_in[0];
    const float* W_ih  = (const float*)d_in[1];
    const float* b_ih  = (const float*)d_in[2];
    const float* W_ho  = (const float*)d_in[3];
    const float* b_ho  = (const float*)d_in[4];
    const float* gamma = (const float*)d_in[5];
    const float* beta  = (const float*)d_in[6];
    float* out = (float*)d_out;

    init_kernel<<<256, 256>>>();
    proj_in_mma<<<dim3((S_LEN * B_SZ) / 128, 2), 256>>>(X, W_ih, b_ih);
    rec_kernel<<<128, 256>>>(W_ih, gamma, beta);
    proj_out_mma<<<(S_LEN * B_SZ) / 128, 256>>>(W_ho, b_ho, out);
}